// round 1
// baseline (speedup 1.0000x reference)
#include <cuda_runtime.h>
#include <cuda_bf16.h>
#include <cstdint>

// Problem constants (B=2, T=2048, D=1024, H=16, HD=64)
#define B_SZ     2
#define T_SEQ    2048
#define D_MODEL  1024
#define NH       16
#define HDIM     64
#define ROWS     (B_SZ * T_SEQ)      // 4096
#define QKV_COLS (3 * D_MODEL)       // 3072

// Scratch (module-load allocated, allowed by harness rules)
__device__ float g_qkv[(size_t)ROWS * QKV_COLS];    // (b, t, 3D): head h -> cols h*192 + {q:0,k:64,v:128}
__device__ float g_vals[(size_t)ROWS * D_MODEL];    // (b, h, t, hd) contiguous == reference reshape

// ---------------------------------------------------------------------------
// fp32 SGEMM: C(M,N) = A(M,K) @ B(K,N), all row-major.
// 128x128 block tile, K-step 8, 256 threads, 8x8 per-thread micro-tile.
// Requires M%128==0, N%128==0, K%8==0 (true for all three calls).
// ---------------------------------------------------------------------------
__global__ __launch_bounds__(256) void sgemm128(const float* __restrict__ A,
                                                const float* __restrict__ B,
                                                float* __restrict__ C,
                                                int M, int N, int K) {
    __shared__ float As[8][128];   // A tile, transposed: As[k][m]
    __shared__ float Bs[8][128];   // B tile: Bs[k][n]

    const int tid = threadIdx.x;
    const int bm  = blockIdx.y * 128;
    const int bn  = blockIdx.x * 128;

    const int tm = (tid >> 4) * 8;     // micro-tile row base within block
    const int tn = (tid & 15) * 8;     // micro-tile col base within block

    const int a_row = tid >> 1;          // 0..127
    const int a_col = (tid & 1) * 4;     // 0 or 4
    const int b_row = tid >> 5;          // 0..7
    const int b_col = (tid & 31) * 4;    // 0..124

    const float* Ag = A + (size_t)(bm + a_row) * K + a_col;
    const float* Bg = B + (size_t)b_row * N + bn + b_col;

    float acc[8][8];
#pragma unroll
    for (int i = 0; i < 8; i++)
#pragma unroll
        for (int j = 0; j < 8; j++) acc[i][j] = 0.0f;

    for (int k0 = 0; k0 < K; k0 += 8) {
        // issue gmem loads before the barrier to overlap with prior compute
        const float4 av = *(const float4*)(Ag + k0);
        const float4 bv = *(const float4*)(Bg + (size_t)k0 * N);
        __syncthreads();   // prior iteration's compute done reading smem
        As[a_col + 0][a_row] = av.x;
        As[a_col + 1][a_row] = av.y;
        As[a_col + 2][a_row] = av.z;
        As[a_col + 3][a_row] = av.w;
        *(float4*)&Bs[b_row][b_col] = bv;
        __syncthreads();

#pragma unroll
        for (int kk = 0; kk < 8; kk++) {
            float ar[8], br[8];
            *(float4*)&ar[0] = *(const float4*)&As[kk][tm];
            *(float4*)&ar[4] = *(const float4*)&As[kk][tm + 4];
            *(float4*)&br[0] = *(const float4*)&Bs[kk][tn];
            *(float4*)&br[4] = *(const float4*)&Bs[kk][tn + 4];
#pragma unroll
            for (int i = 0; i < 8; i++)
#pragma unroll
                for (int j = 0; j < 8; j++)
                    acc[i][j] = fmaf(ar[i], br[j], acc[i][j]);
        }
    }

#pragma unroll
    for (int i = 0; i < 8; i++) {
        float* cp = C + (size_t)(bm + tm + i) * N + bn + tn;
        *(float4*)(cp)     = make_float4(acc[i][0], acc[i][1], acc[i][2], acc[i][3]);
        *(float4*)(cp + 4) = make_float4(acc[i][4], acc[i][5], acc[i][6], acc[i][7]);
    }
}

// ---------------------------------------------------------------------------
// Flash-style causal attention, fp32.
// grid = (T/64 query tiles, B*H). block = 256 threads.
// Thread (g = tid/16, q = tid&15) owns rows [g*4, g*4+4) x cols [q*4, q*4+4)
// of the 64x64 S tile and of the 64x64 O tile.
// smem: sQ (16KB) + sKP (16KB, K tile then reused for P) + sV (16KB) = 48KB.
// ---------------------------------------------------------------------------
__global__ __launch_bounds__(256) void attn_kernel() {
    __shared__ float sQ[64 * 64];
    __shared__ float sKP[64 * 64];   // K tile; overwritten with P after S is computed
    __shared__ float sV[64 * 64];

    const int tid = threadIdx.x;
    const int qt  = blockIdx.x;          // query tile 0..31
    const int bh  = blockIdx.y;          // 0..31
    const int b   = bh >> 4;
    const int h   = bh & 15;

    const size_t tok0 = (size_t)b * T_SEQ;   // first token row of this batch
    const int hoff = h * 192;                // column offset of this head in qkv

    const int g     = tid >> 4;     // row group 0..15
    const int qlane = tid & 15;     // col group 0..15
    const int r0 = g * 4;
    const int c0 = qlane * 4;

    // ---- load Q tile (pre-scaled by 1/sqrt(hd) = 0.125) ----
#pragma unroll
    for (int it = 0; it < 4; it++) {
        const int i  = tid + it * 256;     // 0..1023 (64 rows x 16 float4)
        const int r  = i >> 4;
        const int d4 = (i & 15) << 2;
        const float4 v = *(const float4*)(g_qkv + (tok0 + (size_t)qt * 64 + r) * QKV_COLS + hoff + d4);
        *(float4*)&sQ[r * 64 + d4] =
            make_float4(v.x * 0.125f, v.y * 0.125f, v.z * 0.125f, v.w * 0.125f);
    }

    float o[4][4];
    float mrow[4], lrow[4];
#pragma unroll
    for (int i = 0; i < 4; i++) {
        mrow[i] = -1e30f;
        lrow[i] = 0.0f;
#pragma unroll
        for (int j = 0; j < 4; j++) o[i][j] = 0.0f;
    }

    for (int kt = 0; kt <= qt; kt++) {
        __syncthreads();   // prior PV done reading sKP/sV (also covers Q-load on first iter)

        // ---- load K and V tiles ----
#pragma unroll
        for (int it = 0; it < 4; it++) {
            const int i  = tid + it * 256;
            const int r  = i >> 4;
            const int d4 = (i & 15) << 2;
            const float* src = g_qkv + (tok0 + (size_t)kt * 64 + r) * QKV_COLS + hoff;
            *(float4*)&sKP[r * 64 + d4] = *(const float4*)(src + 64 + d4);
            *(float4*)&sV[r * 64 + d4]  = *(const float4*)(src + 128 + d4);
        }
        __syncthreads();

        // ---- S = (Q/8) K^T, 4x4 micro-tile ----
        float s[4][4];
#pragma unroll
        for (int i = 0; i < 4; i++)
#pragma unroll
            for (int j = 0; j < 4; j++) s[i][j] = 0.0f;

#pragma unroll
        for (int d = 0; d < 64; d += 4) {
            float4 qv[4], kv[4];
#pragma unroll
            for (int i = 0; i < 4; i++) qv[i] = *(const float4*)&sQ[(r0 + i) * 64 + d];
#pragma unroll
            for (int j = 0; j < 4; j++) kv[j] = *(const float4*)&sKP[(c0 + j) * 64 + d];
#pragma unroll
            for (int i = 0; i < 4; i++)
#pragma unroll
                for (int j = 0; j < 4; j++) {
                    s[i][j] = fmaf(qv[i].x, kv[j].x, s[i][j]);
                    s[i][j] = fmaf(qv[i].y, kv[j].y, s[i][j]);
                    s[i][j] = fmaf(qv[i].z, kv[j].z, s[i][j]);
                    s[i][j] = fmaf(qv[i].w, kv[j].w, s[i][j]);
                }
        }

        // ---- causal mask on the diagonal tile ----
        if (kt == qt) {
#pragma unroll
            for (int i = 0; i < 4; i++)
#pragma unroll
                for (int j = 0; j < 4; j++)
                    if (c0 + j > r0 + i) s[i][j] = -1e30f;
        }

        // ---- online softmax update (reduce across the 16 lanes of each row group) ----
#pragma unroll
        for (int i = 0; i < 4; i++) {
            float mx = fmaxf(fmaxf(s[i][0], s[i][1]), fmaxf(s[i][2], s[i][3]));
            mx = fmaxf(mx, __shfl_xor_sync(0xffffffffu, mx, 1));
            mx = fmaxf(mx, __shfl_xor_sync(0xffffffffu, mx, 2));
            mx = fmaxf(mx, __shfl_xor_sync(0xffffffffu, mx, 4));
            mx = fmaxf(mx, __shfl_xor_sync(0xffffffffu, mx, 8));

            const float mnew = fmaxf(mrow[i], mx);
            const float sc   = __expf(mrow[i] - mnew);

            float psum = 0.0f;
#pragma unroll
            for (int j = 0; j < 4; j++) {
                s[i][j] = __expf(s[i][j] - mnew);
                psum += s[i][j];
            }
            psum += __shfl_xor_sync(0xffffffffu, psum, 1);
            psum += __shfl_xor_sync(0xffffffffu, psum, 2);
            psum += __shfl_xor_sync(0xffffffffu, psum, 4);
            psum += __shfl_xor_sync(0xffffffffu, psum, 8);

            lrow[i] = lrow[i] * sc + psum;
            mrow[i] = mnew;
#pragma unroll
            for (int j = 0; j < 4; j++) o[i][j] *= sc;
        }

        __syncthreads();   // everyone done reading sKP as K
        // ---- write P into sKP ----
#pragma unroll
        for (int i = 0; i < 4; i++)
#pragma unroll
            for (int j = 0; j < 4; j++)
                sKP[(r0 + i) * 64 + c0 + j] = s[i][j];
        __syncthreads();

        // ---- O += P V ----
#pragma unroll 8
        for (int k = 0; k < 64; k++) {
            const float4 vv = *(const float4*)&sV[k * 64 + c0];
#pragma unroll
            for (int i = 0; i < 4; i++) {
                const float p = sKP[(r0 + i) * 64 + k];
                o[i][0] = fmaf(p, vv.x, o[i][0]);
                o[i][1] = fmaf(p, vv.y, o[i][1]);
                o[i][2] = fmaf(p, vv.z, o[i][2]);
                o[i][3] = fmaf(p, vv.w, o[i][3]);
            }
        }
    }

    // ---- normalize and write to (b,h,t,hd)-contiguous vals ----
#pragma unroll
    for (int i = 0; i < 4; i++) {
        const float inv = 1.0f / lrow[i];
        float* dst = g_vals + ((size_t)bh * T_SEQ + (size_t)qt * 64 + r0 + i) * HDIM + c0;
        *(float4*)dst = make_float4(o[i][0] * inv, o[i][1] * inv, o[i][2] * inv, o[i][3] * inv);
    }
}

// ---------------------------------------------------------------------------
// kernel_launch: qkv GEMM -> attention -> output GEMM
// ---------------------------------------------------------------------------
extern "C" void kernel_launch(void* const* d_in, const int* in_sizes, int n_in,
                              void* d_out, int out_size) {
    const float* x     = (const float*)d_in[0];   // (B, T, D)
    const float* wqkv  = (const float*)d_in[1];   // (D, 3D)
    const float* wout  = (const float*)d_in[2];   // (D, D)
    float*       out   = (float*)d_out;           // (B, T, D)

    float* qkv_ptr  = nullptr;
    float* vals_ptr = nullptr;
    cudaGetSymbolAddress((void**)&qkv_ptr,  g_qkv);
    cudaGetSymbolAddress((void**)&vals_ptr, g_vals);

    // 1) qkv = x @ w_qkv : (4096, 1024) @ (1024, 3072)
    sgemm128<<<dim3(QKV_COLS / 128, ROWS / 128), 256>>>(x, wqkv, qkv_ptr,
                                                        ROWS, QKV_COLS, D_MODEL);

    // 2) causal flash attention -> g_vals in (b,h,t,hd) order
    attn_kernel<<<dim3(T_SEQ / 64, B_SZ * NH), 256>>>();

    // 3) out = vals @ w_out : (4096, 1024) @ (1024, 1024)
    sgemm128<<<dim3(D_MODEL / 128, ROWS / 128), 256>>>(vals_ptr, wout, out,
                                                       ROWS, D_MODEL, D_MODEL);
}

// round 2
// speedup vs baseline: 3.1311x; 3.1311x over previous
#include <cuda_runtime.h>
#include <cuda_bf16.h>
#include <cstdint>

// Problem constants (B=2, T=2048, D=1024, H=16, HD=64)
#define B_SZ     2
#define T_SEQ    2048
#define D_MODEL  1024
#define NH       16
#define HDIM     64
#define ROWS     (B_SZ * T_SEQ)      // 4096
#define QKV_COLS (3 * D_MODEL)       // 3072
#define BH       (B_SZ * NH)         // 32

// ---------------------------------------------------------------------------
// Scratch (__device__ globals; no runtime allocation)
// ---------------------------------------------------------------------------
__device__ float         g_qkv[(size_t)ROWS * QKV_COLS];          // fp32 qkv
__device__ __nv_bfloat16 gXh[(size_t)ROWS * D_MODEL];             // x split
__device__ __nv_bfloat16 gXl[(size_t)ROWS * D_MODEL];
__device__ __nv_bfloat16 gWqh[(size_t)QKV_COLS * D_MODEL];        // w_qkv^T split (N x K)
__device__ __nv_bfloat16 gWql[(size_t)QKV_COLS * D_MODEL];
__device__ __nv_bfloat16 gWoh[(size_t)D_MODEL * D_MODEL];         // w_out^T split
__device__ __nv_bfloat16 gWol[(size_t)D_MODEL * D_MODEL];
__device__ __nv_bfloat16 gQh[(size_t)BH * T_SEQ * HDIM];          // per-head Q (scaled), split
__device__ __nv_bfloat16 gQl[(size_t)BH * T_SEQ * HDIM];
__device__ __nv_bfloat16 gKh[(size_t)BH * T_SEQ * HDIM];          // per-head K, split
__device__ __nv_bfloat16 gKl[(size_t)BH * T_SEQ * HDIM];
__device__ __nv_bfloat16 gVth[(size_t)BH * HDIM * T_SEQ];         // per-head V transposed (d, t)
__device__ __nv_bfloat16 gVtl[(size_t)BH * HDIM * T_SEQ];
__device__ __nv_bfloat16 gVAh[(size_t)ROWS * D_MODEL];            // attention output split
__device__ __nv_bfloat16 gVAl[(size_t)ROWS * D_MODEL];

// ---------------------------------------------------------------------------
// mma.sync m16n8k16 bf16 wrapper (fp32 accum)
// ---------------------------------------------------------------------------
__device__ __forceinline__ void mma16816(float c[4], const uint32_t a[4],
                                         uint32_t b0, uint32_t b1) {
    asm volatile(
        "mma.sync.aligned.m16n8k16.row.col.f32.bf16.bf16.f32 "
        "{%0,%1,%2,%3}, {%4,%5,%6,%7}, {%8,%9}, {%0,%1,%2,%3};\n"
        : "+f"(c[0]), "+f"(c[1]), "+f"(c[2]), "+f"(c[3])
        : "r"(a[0]), "r"(a[1]), "r"(a[2]), "r"(a[3]), "r"(b0), "r"(b1));
}

__device__ __forceinline__ uint32_t pack_bf16(float lo, float hi) {
    __nv_bfloat162 h = __floats2bfloat162_rn(lo, hi);
    return *reinterpret_cast<uint32_t*>(&h);
}

// ---------------------------------------------------------------------------
// Elementwise hi/lo split (row-major, same layout): fp32 -> 2x bf16
// ---------------------------------------------------------------------------
__global__ void split_rm(const float4* __restrict__ A, uint2* __restrict__ H,
                         uint2* __restrict__ L, int n4) {
    int i = blockIdx.x * blockDim.x + threadIdx.x;
    if (i >= n4) return;
    float4 v = A[i];
    __nv_bfloat162 h0 = __floats2bfloat162_rn(v.x, v.y);
    __nv_bfloat162 h1 = __floats2bfloat162_rn(v.z, v.w);
    __nv_bfloat162 l0 = __floats2bfloat162_rn(v.x - __bfloat162float(h0.x),
                                              v.y - __bfloat162float(h0.y));
    __nv_bfloat162 l1 = __floats2bfloat162_rn(v.z - __bfloat162float(h1.x),
                                              v.w - __bfloat162float(h1.y));
    H[i] = make_uint2(*reinterpret_cast<uint32_t*>(&h0), *reinterpret_cast<uint32_t*>(&h1));
    L[i] = make_uint2(*reinterpret_cast<uint32_t*>(&l0), *reinterpret_cast<uint32_t*>(&l1));
}

// ---------------------------------------------------------------------------
// Transpose + split: W (K x N) fp32 -> TH/TL (N x K) bf16
// ---------------------------------------------------------------------------
__global__ __launch_bounds__(256) void split_wt(const float* __restrict__ W,
                                                __nv_bfloat16* __restrict__ TH,
                                                __nv_bfloat16* __restrict__ TL,
                                                int K, int N) {
    __shared__ float tile[32][33];
    const int kb = blockIdx.x * 32, nb = blockIdx.y * 32;
    const int tx = threadIdx.x & 31, ty = threadIdx.x >> 5;
#pragma unroll
    for (int r = ty; r < 32; r += 8)
        tile[r][tx] = W[(size_t)(kb + r) * N + nb + tx];
    __syncthreads();
#pragma unroll
    for (int r = ty; r < 32; r += 8) {
        float v = tile[tx][r];
        __nv_bfloat16 h = __float2bfloat16(v);
        TH[(size_t)(nb + r) * K + kb + tx] = h;
        TL[(size_t)(nb + r) * K + kb + tx] = __float2bfloat16(v - __bfloat162float(h));
    }
}

// ---------------------------------------------------------------------------
// bf16x3 GEMM: C (M x N) fp32 = (Ah+Al)(M x K) @ (Bh+Bl)^T where B stored (N x K).
// Block 128x128, K-step 32, 256 threads (8 warps as 2m x 4n, warp tile 64x32).
// ---------------------------------------------------------------------------
__global__ __launch_bounds__(256) void gemm_bf16x3(
    const __nv_bfloat16* __restrict__ Ah, const __nv_bfloat16* __restrict__ Al,
    const __nv_bfloat16* __restrict__ Bh, const __nv_bfloat16* __restrict__ Bl,
    float* __restrict__ C, int M, int N, int K) {
    // row stride 40 bf16 (20 words) for conflict-free fragment reads
    __shared__ __nv_bfloat16 sAh[128 * 40], sAl[128 * 40];
    __shared__ __nv_bfloat16 sBh[128 * 40], sBl[128 * 40];

    const int tid  = threadIdx.x;
    const int lane = tid & 31;
    const int warp = tid >> 5;
    const int g = lane >> 2, t = lane & 3;
    const int wm = warp >> 2, wn = warp & 3;     // 2 x 4 warp grid
    const int bm = blockIdx.y * 128, bn = blockIdx.x * 128;

    float c[4][4][4];
#pragma unroll
    for (int mt = 0; mt < 4; mt++)
#pragma unroll
        for (int nt = 0; nt < 4; nt++)
#pragma unroll
            for (int i = 0; i < 4; i++) c[mt][nt][i] = 0.0f;

    const int row_l = tid >> 2;            // 0..63  (two iterations cover 128)
    const int cf4   = (tid & 3) * 8;       // bf16 column of the 16B chunk

    for (int k0 = 0; k0 < K; k0 += 32) {
        // stage loads in registers
        uint4 va[2], vb[2], vc[2], vd[2];
#pragma unroll
        for (int r = 0; r < 2; r++) {
            const int row = row_l + r * 64;
            va[r] = *reinterpret_cast<const uint4*>(Ah + (size_t)(bm + row) * K + k0 + cf4);
            vb[r] = *reinterpret_cast<const uint4*>(Al + (size_t)(bm + row) * K + k0 + cf4);
            vc[r] = *reinterpret_cast<const uint4*>(Bh + (size_t)(bn + row) * K + k0 + cf4);
            vd[r] = *reinterpret_cast<const uint4*>(Bl + (size_t)(bn + row) * K + k0 + cf4);
        }
        __syncthreads();   // previous iteration's reads done
#pragma unroll
        for (int r = 0; r < 2; r++) {
            const int row = row_l + r * 64;
            *reinterpret_cast<uint4*>(&sAh[row * 40 + cf4]) = va[r];
            *reinterpret_cast<uint4*>(&sAl[row * 40 + cf4]) = vb[r];
            *reinterpret_cast<uint4*>(&sBh[row * 40 + cf4]) = vc[r];
            *reinterpret_cast<uint4*>(&sBl[row * 40 + cf4]) = vd[r];
        }
        __syncthreads();

        const uint32_t* wAh = reinterpret_cast<const uint32_t*>(sAh);
        const uint32_t* wAl = reinterpret_cast<const uint32_t*>(sAl);
        const uint32_t* wBh = reinterpret_cast<const uint32_t*>(sBh);
        const uint32_t* wBl = reinterpret_cast<const uint32_t*>(sBl);

#pragma unroll
        for (int kt = 0; kt < 2; kt++) {
            uint32_t afh[4][4], afl[4][4];
#pragma unroll
            for (int mt = 0; mt < 4; mt++) {
                const int base = (wm * 64 + mt * 16 + g) * 20 + kt * 8 + t;
                afh[mt][0] = wAh[base];       afh[mt][1] = wAh[base + 160];
                afh[mt][2] = wAh[base + 4];   afh[mt][3] = wAh[base + 164];
                afl[mt][0] = wAl[base];       afl[mt][1] = wAl[base + 160];
                afl[mt][2] = wAl[base + 4];   afl[mt][3] = wAl[base + 164];
            }
#pragma unroll
            for (int nt = 0; nt < 4; nt++) {
                const int nb = (wn * 32 + nt * 8 + g) * 20 + kt * 8 + t;
                const uint32_t b0h = wBh[nb], b1h = wBh[nb + 4];
                const uint32_t b0l = wBl[nb], b1l = wBl[nb + 4];
#pragma unroll
                for (int mt = 0; mt < 4; mt++) {
                    mma16816(c[mt][nt], afh[mt], b0h, b1h);
                    mma16816(c[mt][nt], afh[mt], b0l, b1l);
                    mma16816(c[mt][nt], afl[mt], b0h, b1h);
                }
            }
        }
    }

    // epilogue
#pragma unroll
    for (int mt = 0; mt < 4; mt++) {
        const int row = bm + wm * 64 + mt * 16 + g;
#pragma unroll
        for (int nt = 0; nt < 4; nt++) {
            const int col = bn + wn * 32 + nt * 8 + 2 * t;
            *reinterpret_cast<float2*>(&C[(size_t)row * N + col]) =
                make_float2(c[mt][nt][0], c[mt][nt][1]);
            *reinterpret_cast<float2*>(&C[(size_t)(row + 8) * N + col]) =
                make_float2(c[mt][nt][2], c[mt][nt][3]);
        }
    }
}

// ---------------------------------------------------------------------------
// Attention prep: g_qkv -> per-head split Q (scaled), K, and transposed V.
// grid (T/128, BH), 256 threads.
// ---------------------------------------------------------------------------
__global__ __launch_bounds__(256) void attn_prep() {
    __shared__ float sV[128][65];
    const int tid = threadIdx.x;
    const int bh = blockIdx.y;
    const int b = bh >> 4, h = bh & 15;
    const int t0 = blockIdx.x * 128;
    const float* base = g_qkv + ((size_t)(b * T_SEQ + t0)) * QKV_COLS + h * 192;

    for (int i = tid; i < 128 * 64; i += 256) {
        const int tt = i >> 6, d = i & 63;
        const float* rp = base + (size_t)tt * QKV_COLS;
        const size_t o = ((size_t)bh * T_SEQ + t0 + tt) * HDIM + d;
        float q = rp[d] * 0.125f;
        __nv_bfloat16 qh = __float2bfloat16(q);
        gQh[o] = qh; gQl[o] = __float2bfloat16(q - __bfloat162float(qh));
        float k = rp[64 + d];
        __nv_bfloat16 kh = __float2bfloat16(k);
        gKh[o] = kh; gKl[o] = __float2bfloat16(k - __bfloat162float(kh));
        sV[tt][d] = rp[128 + d];
    }
    __syncthreads();
    for (int j = tid; j < 64 * 128; j += 256) {
        const int d = j >> 7, tt = j & 127;
        float v = sV[tt][d];
        __nv_bfloat16 vh = __float2bfloat16(v);
        const size_t o = ((size_t)bh * HDIM + d) * T_SEQ + t0 + tt;
        gVth[o] = vh; gVtl[o] = __float2bfloat16(v - __bfloat162float(vh));
    }
}

// ---------------------------------------------------------------------------
// Flash attention with bf16 mma (x3 for S and PV). grid (T/128, BH), 256 thr.
// Warp w owns query rows [qb+16w, qb+16w+16). Softmax fully warp-local.
// Writes attention output directly as hi/lo bf16 split for the proj GEMM.
// ---------------------------------------------------------------------------
__global__ __launch_bounds__(256) void attn_mma() {
    __shared__ __nv_bfloat16 sKh[64 * 72], sKl[64 * 72];
    __shared__ __nv_bfloat16 sVh[64 * 72], sVl[64 * 72];

    const int tid = threadIdx.x;
    const int lane = tid & 31, warp = tid >> 5;
    const int g = lane >> 2, t = lane & 3;
    const int qblk = blockIdx.x, bh = blockIdx.y;
    const int qb = qblk * 128;
    const int qrow = qb + warp * 16 + g;

    // Q fragments (held for the whole kernel)
    const uint32_t* gqh = reinterpret_cast<const uint32_t*>(gQh + (size_t)bh * T_SEQ * HDIM);
    const uint32_t* gql = reinterpret_cast<const uint32_t*>(gQl + (size_t)bh * T_SEQ * HDIM);
    uint32_t qfh[4][4], qfl[4][4];
#pragma unroll
    for (int k4 = 0; k4 < 4; k4++) {
        const int w0 = qrow * 32 + k4 * 8 + t;
        qfh[k4][0] = gqh[w0];       qfh[k4][1] = gqh[w0 + 256];
        qfh[k4][2] = gqh[w0 + 4];   qfh[k4][3] = gqh[w0 + 260];
        qfl[k4][0] = gql[w0];       qfl[k4][1] = gql[w0 + 256];
        qfl[k4][2] = gql[w0 + 4];   qfl[k4][3] = gql[w0 + 260];
    }

    float o[8][4];
#pragma unroll
    for (int i = 0; i < 8; i++)
#pragma unroll
        for (int j = 0; j < 4; j++) o[i][j] = 0.0f;
    float m0 = -1e30f, m1 = -1e30f, l0 = 0.0f, l1 = 0.0f;

    const int nkt = 2 * qblk + 2;
    const int row_l = tid >> 3;          // 0..31 (two iterations cover 64)
    const int c8 = (tid & 7) * 8;

    for (int kt = 0; kt < nkt; kt++) {
        // ---- stage K / V tiles ----
        uint4 ra[2], rb[2], rc[2], rd[2];
#pragma unroll
        for (int r = 0; r < 2; r++) {
            const int row = row_l + r * 32;
            const size_t kk = ((size_t)bh * T_SEQ + kt * 64 + row) * HDIM + c8;
            const size_t vv = ((size_t)bh * HDIM + row) * T_SEQ + kt * 64 + c8;
            ra[r] = *reinterpret_cast<const uint4*>(gKh + kk);
            rb[r] = *reinterpret_cast<const uint4*>(gKl + kk);
            rc[r] = *reinterpret_cast<const uint4*>(gVth + vv);
            rd[r] = *reinterpret_cast<const uint4*>(gVtl + vv);
        }
        __syncthreads();
#pragma unroll
        for (int r = 0; r < 2; r++) {
            const int row = row_l + r * 32;
            *reinterpret_cast<uint4*>(&sKh[row * 72 + c8]) = ra[r];
            *reinterpret_cast<uint4*>(&sKl[row * 72 + c8]) = rb[r];
            *reinterpret_cast<uint4*>(&sVh[row * 72 + c8]) = rc[r];
            *reinterpret_cast<uint4*>(&sVl[row * 72 + c8]) = rd[r];
        }
        __syncthreads();

        const uint32_t* wKh = reinterpret_cast<const uint32_t*>(sKh);
        const uint32_t* wKl = reinterpret_cast<const uint32_t*>(sKl);
        const uint32_t* wVh = reinterpret_cast<const uint32_t*>(sVh);
        const uint32_t* wVl = reinterpret_cast<const uint32_t*>(sVl);

        // ---- S = Q K^T (x3) ----
        float s[8][4];
#pragma unroll
        for (int i = 0; i < 8; i++)
#pragma unroll
            for (int j = 0; j < 4; j++) s[i][j] = 0.0f;

#pragma unroll
        for (int k4 = 0; k4 < 4; k4++) {
#pragma unroll
            for (int nt = 0; nt < 8; nt++) {
                const int kb = (nt * 8 + g) * 36 + k4 * 8 + t;
                const uint32_t b0h = wKh[kb], b1h = wKh[kb + 4];
                const uint32_t b0l = wKl[kb], b1l = wKl[kb + 4];
                mma16816(s[nt], qfh[k4], b0h, b1h);
                mma16816(s[nt], qfh[k4], b0l, b1l);
                mma16816(s[nt], qfl[k4], b0h, b1h);
            }
        }

        // ---- causal mask (only diagonal tiles) ----
        if (kt >= 2 * qblk) {
#pragma unroll
            for (int nt = 0; nt < 8; nt++) {
                const int colb = kt * 64 + nt * 8 + 2 * t;
                if (colb     > qrow)     s[nt][0] = -1e30f;
                if (colb + 1 > qrow)     s[nt][1] = -1e30f;
                if (colb     > qrow + 8) s[nt][2] = -1e30f;
                if (colb + 1 > qrow + 8) s[nt][3] = -1e30f;
            }
        }

        // ---- online softmax (warp-local rows) ----
        float mx0 = -1e30f, mx1 = -1e30f;
#pragma unroll
        for (int nt = 0; nt < 8; nt++) {
            mx0 = fmaxf(mx0, fmaxf(s[nt][0], s[nt][1]));
            mx1 = fmaxf(mx1, fmaxf(s[nt][2], s[nt][3]));
        }
        mx0 = fmaxf(mx0, __shfl_xor_sync(0xffffffffu, mx0, 1));
        mx0 = fmaxf(mx0, __shfl_xor_sync(0xffffffffu, mx0, 2));
        mx1 = fmaxf(mx1, __shfl_xor_sync(0xffffffffu, mx1, 1));
        mx1 = fmaxf(mx1, __shfl_xor_sync(0xffffffffu, mx1, 2));
        const float mn0 = fmaxf(m0, mx0), mn1 = fmaxf(m1, mx1);
        const float sc0 = __expf(m0 - mn0), sc1 = __expf(m1 - mn1);
        float sum0 = 0.0f, sum1 = 0.0f;
#pragma unroll
        for (int nt = 0; nt < 8; nt++) {
            s[nt][0] = __expf(s[nt][0] - mn0); sum0 += s[nt][0];
            s[nt][1] = __expf(s[nt][1] - mn0); sum0 += s[nt][1];
            s[nt][2] = __expf(s[nt][2] - mn1); sum1 += s[nt][2];
            s[nt][3] = __expf(s[nt][3] - mn1); sum1 += s[nt][3];
        }
        sum0 += __shfl_xor_sync(0xffffffffu, sum0, 1);
        sum0 += __shfl_xor_sync(0xffffffffu, sum0, 2);
        sum1 += __shfl_xor_sync(0xffffffffu, sum1, 1);
        sum1 += __shfl_xor_sync(0xffffffffu, sum1, 2);
        l0 = l0 * sc0 + sum0; m0 = mn0;
        l1 = l1 * sc1 + sum1; m1 = mn1;
#pragma unroll
        for (int nt = 0; nt < 8; nt++) {
            o[nt][0] *= sc0; o[nt][1] *= sc0;
            o[nt][2] *= sc1; o[nt][3] *= sc1;
        }

        // ---- O += P V (x3); P fragments built in registers ----
#pragma unroll
        for (int kp = 0; kp < 4; kp++) {
            const float* pa = s[2 * kp];
            const float* pb = s[2 * kp + 1];
            uint32_t ah[4], al[4];
            {
                __nv_bfloat162 h0 = __floats2bfloat162_rn(pa[0], pa[1]);
                __nv_bfloat162 h1 = __floats2bfloat162_rn(pa[2], pa[3]);
                __nv_bfloat162 h2 = __floats2bfloat162_rn(pb[0], pb[1]);
                __nv_bfloat162 h3 = __floats2bfloat162_rn(pb[2], pb[3]);
                ah[0] = *reinterpret_cast<uint32_t*>(&h0);
                ah[1] = *reinterpret_cast<uint32_t*>(&h1);
                ah[2] = *reinterpret_cast<uint32_t*>(&h2);
                ah[3] = *reinterpret_cast<uint32_t*>(&h3);
                __nv_bfloat162 e0 = __floats2bfloat162_rn(pa[0] - __bfloat162float(h0.x),
                                                          pa[1] - __bfloat162float(h0.y));
                __nv_bfloat162 e1 = __floats2bfloat162_rn(pa[2] - __bfloat162float(h1.x),
                                                          pa[3] - __bfloat162float(h1.y));
                __nv_bfloat162 e2 = __floats2bfloat162_rn(pb[0] - __bfloat162float(h2.x),
                                                          pb[1] - __bfloat162float(h2.y));
                __nv_bfloat162 e3 = __floats2bfloat162_rn(pb[2] - __bfloat162float(h3.x),
                                                          pb[3] - __bfloat162float(h3.y));
                al[0] = *reinterpret_cast<uint32_t*>(&e0);
                al[1] = *reinterpret_cast<uint32_t*>(&e1);
                al[2] = *reinterpret_cast<uint32_t*>(&e2);
                al[3] = *reinterpret_cast<uint32_t*>(&e3);
            }
#pragma unroll
            for (int nd = 0; nd < 8; nd++) {
                const int vb = (nd * 8 + g) * 36 + kp * 8 + t;
                const uint32_t b0h = wVh[vb], b1h = wVh[vb + 4];
                const uint32_t b0l = wVl[vb], b1l = wVl[vb + 4];
                mma16816(o[nd], ah, b0h, b1h);
                mma16816(o[nd], ah, b0l, b1l);
                mma16816(o[nd], al, b0h, b1h);
            }
        }
        __syncthreads();   // done with smem before next tile load
    }

    // ---- epilogue: normalize and emit hi/lo bf16 split for proj GEMM ----
    const float inv0 = 1.0f / l0, inv1 = 1.0f / l1;
#pragma unroll
    for (int nd = 0; nd < 8; nd++) {
        const size_t flat = ((size_t)bh * T_SEQ + qb + warp * 16 + g) * HDIM + nd * 8 + 2 * t;
        {
            const float v0 = o[nd][0] * inv0, v1 = o[nd][1] * inv0;
            __nv_bfloat162 hh = __floats2bfloat162_rn(v0, v1);
            *reinterpret_cast<uint32_t*>(gVAh + flat) = *reinterpret_cast<uint32_t*>(&hh);
            __nv_bfloat162 ll = __floats2bfloat162_rn(v0 - __bfloat162float(hh.x),
                                                      v1 - __bfloat162float(hh.y));
            *reinterpret_cast<uint32_t*>(gVAl + flat) = *reinterpret_cast<uint32_t*>(&ll);
        }
        {
            const size_t f8 = flat + 8 * HDIM;
            const float v0 = o[nd][2] * inv1, v1 = o[nd][3] * inv1;
            __nv_bfloat162 hh = __floats2bfloat162_rn(v0, v1);
            *reinterpret_cast<uint32_t*>(gVAh + f8) = *reinterpret_cast<uint32_t*>(&hh);
            __nv_bfloat162 ll = __floats2bfloat162_rn(v0 - __bfloat162float(hh.x),
                                                      v1 - __bfloat162float(hh.y));
            *reinterpret_cast<uint32_t*>(gVAl + f8) = *reinterpret_cast<uint32_t*>(&ll);
        }
    }
}

// ---------------------------------------------------------------------------
// kernel_launch
// ---------------------------------------------------------------------------
extern "C" void kernel_launch(void* const* d_in, const int* in_sizes, int n_in,
                              void* d_out, int out_size) {
    const float* x    = (const float*)d_in[0];   // (B,T,D)
    const float* wqkv = (const float*)d_in[1];   // (D, 3D)
    const float* wout = (const float*)d_in[2];   // (D, D)
    float*       out  = (float*)d_out;

    float* qkv; __nv_bfloat16 *xh, *xl, *wqh, *wql, *woh, *wol, *vah, *vaL;
    cudaGetSymbolAddress((void**)&qkv, g_qkv);
    cudaGetSymbolAddress((void**)&xh,  gXh);  cudaGetSymbolAddress((void**)&xl,  gXl);
    cudaGetSymbolAddress((void**)&wqh, gWqh); cudaGetSymbolAddress((void**)&wql, gWql);
    cudaGetSymbolAddress((void**)&woh, gWoh); cudaGetSymbolAddress((void**)&wol, gWol);
    cudaGetSymbolAddress((void**)&vah, gVAh); cudaGetSymbolAddress((void**)&vaL, gVAl);

    // 1) splits of inputs
    const int n4x = ROWS * D_MODEL / 4;
    split_rm<<<(n4x + 255) / 256, 256>>>((const float4*)x, (uint2*)xh, (uint2*)xl, n4x);
    split_wt<<<dim3(D_MODEL / 32, QKV_COLS / 32), 256>>>(wqkv, wqh, wql, D_MODEL, QKV_COLS);
    split_wt<<<dim3(D_MODEL / 32, D_MODEL / 32), 256>>>(wout, woh, wol, D_MODEL, D_MODEL);

    // 2) qkv = x @ w_qkv
    gemm_bf16x3<<<dim3(QKV_COLS / 128, ROWS / 128), 256>>>(xh, xl, wqh, wql, qkv,
                                                           ROWS, QKV_COLS, D_MODEL);
    // 3) per-head prep (scale+split Q, split K, transpose+split V)
    attn_prep<<<dim3(T_SEQ / 128, BH), 256>>>();

    // 4) flash attention -> gVAh/gVAl (bf16 split, (b,h,t,hd) flat order)
    attn_mma<<<dim3(T_SEQ / 128, BH), 256>>>();

    // 5) out = vals @ w_out
    gemm_bf16x3<<<dim3(D_MODEL / 128, ROWS / 128), 256>>>(vah, vaL, woh, wol, out,
                                                          ROWS, D_MODEL, D_MODEL);
}

// round 5
// speedup vs baseline: 3.6842x; 1.1766x over previous
#include <cuda_runtime.h>
#include <cuda_bf16.h>
#include <cstdint>

// Problem constants (B=2, T=2048, D=1024, H=16, HD=64)
#define B_SZ     2
#define T_SEQ    2048
#define D_MODEL  1024
#define NH       16
#define HDIM     64
#define ROWS     (B_SZ * T_SEQ)      // 4096
#define QKV_COLS (3 * D_MODEL)       // 3072
#define BH       (B_SZ * NH)         // 32

// ---------------------------------------------------------------------------
// Scratch (__device__ globals; no runtime allocation)
// ---------------------------------------------------------------------------
__device__ float         g_qkv[(size_t)ROWS * QKV_COLS];
__device__ __nv_bfloat16 gXh[(size_t)ROWS * D_MODEL];
__device__ __nv_bfloat16 gXl[(size_t)ROWS * D_MODEL];
__device__ __nv_bfloat16 gWqh[(size_t)QKV_COLS * D_MODEL];   // w_qkv^T (N x K)
__device__ __nv_bfloat16 gWql[(size_t)QKV_COLS * D_MODEL];
__device__ __nv_bfloat16 gWoh[(size_t)D_MODEL * D_MODEL];    // w_out^T (N x K)
__device__ __nv_bfloat16 gWol[(size_t)D_MODEL * D_MODEL];
__device__ __nv_bfloat16 gQh[(size_t)BH * T_SEQ * HDIM];
__device__ __nv_bfloat16 gQl[(size_t)BH * T_SEQ * HDIM];
__device__ __nv_bfloat16 gKh[(size_t)BH * T_SEQ * HDIM];
__device__ __nv_bfloat16 gKl[(size_t)BH * T_SEQ * HDIM];
__device__ __nv_bfloat16 gVth[(size_t)BH * HDIM * T_SEQ];
__device__ __nv_bfloat16 gVtl[(size_t)BH * HDIM * T_SEQ];
__device__ __nv_bfloat16 gVAh[(size_t)ROWS * D_MODEL];
__device__ __nv_bfloat16 gVAl[(size_t)ROWS * D_MODEL];

// ---------------------------------------------------------------------------
// PTX helpers (sm_80-compatible only — tcgen05 rejected by this toolchain)
// ---------------------------------------------------------------------------
__device__ __forceinline__ uint32_t smem_u32(const void* p) {
    uint32_t a;
    asm("{ .reg .u64 t; cvta.to.shared.u64 t, %1; cvt.u32.u64 %0, t; }" : "=r"(a) : "l"(p));
    return a;
}
__device__ __forceinline__ void cp_async16(uint32_t dst, const void* src) {
    asm volatile("cp.async.cg.shared.global [%0], [%1], 16;\n" :: "r"(dst), "l"(src));
}
__device__ __forceinline__ void cp_commit() { asm volatile("cp.async.commit_group;\n"); }
template <int N>
__device__ __forceinline__ void cp_wait() { asm volatile("cp.async.wait_group %0;\n" :: "n"(N)); }

__device__ __forceinline__ void mma16816(float c[4], const uint32_t a[4],
                                         uint32_t b0, uint32_t b1) {
    asm volatile(
        "mma.sync.aligned.m16n8k16.row.col.f32.bf16.bf16.f32 "
        "{%0,%1,%2,%3}, {%4,%5,%6,%7}, {%8,%9}, {%0,%1,%2,%3};\n"
        : "+f"(c[0]), "+f"(c[1]), "+f"(c[2]), "+f"(c[3])
        : "r"(a[0]), "r"(a[1]), "r"(a[2]), "r"(a[3]), "r"(b0), "r"(b1));
}

// ===========================================================================
// bf16x3 GEMM v2: C(M,N) fp32 = (Ah+Al)(MxK) @ (Bh+Bl)^T, B stored (N x K).
// 128x128 tile, K-chunk 32, 3-stage cp.async pipeline, one sync per chunk.
// smem row stride 80 B (20 words): 16B-aligned for cp.async AND conflict-free
// for the scalar fragment loads (g*20+t mod 32 hits 32 distinct banks).
// ===========================================================================
#define GS          3                       // stages
#define GMAT        10240                   // 128 rows * 80 B, per matrix
#define GSTAGE      (4 * GMAT)              // Ah,Al,Bh,Bl
#define GEMM_SMEM   (GS * GSTAGE)           // 122880 B

__global__ __launch_bounds__(256, 1) void gemm_bf16x3(
    const __nv_bfloat16* __restrict__ Ah, const __nv_bfloat16* __restrict__ Al,
    const __nv_bfloat16* __restrict__ Bh, const __nv_bfloat16* __restrict__ Bl,
    float* __restrict__ C, int M, int N, int K) {
    extern __shared__ __align__(16) char smem[];
    const uint32_t sb = smem_u32(smem);

    const int tid  = threadIdx.x;
    const int lane = tid & 31;
    const int warp = tid >> 5;
    const int g = lane >> 2, t = lane & 3;
    const int wm = warp >> 2, wn = warp & 3;         // 2 x 4 warp grid
    const int bm = blockIdx.y * 128, bn = blockIdx.x * 128;
    const int nk = K >> 5;                            // chunks of 32

    float c[4][4][4];
#pragma unroll
    for (int mt = 0; mt < 4; mt++)
#pragma unroll
        for (int nt = 0; nt < 4; nt++)
#pragma unroll
            for (int i = 0; i < 4; i++) c[mt][nt][i] = 0.0f;

    // per-thread cp.async assignment: 2 iterations x (row, 16B chunk) per matrix
    const int r_a  = tid >> 1;              // with j: rows tid>>1 handled twice? no:
    // i = tid + j*256, j<2 -> i in 0..511; row = i>>2 (0..127), ch = i&3 (0..3)
    auto load_stage = [&](int s, int k0) {
        const uint32_t stage = sb + s * GSTAGE;
#pragma unroll
        for (int j = 0; j < 2; j++) {
            const int i   = tid + j * 256;
            const int row = i >> 2;
            const int ch  = i & 3;
            const uint32_t dst = stage + row * 80 + ch * 16;
            const int kcol = k0 + ch * 8;
            const size_t ga = (size_t)(bm + row) * K + kcol;
            const size_t gb = (size_t)(bn + row) * K + kcol;
            cp_async16(dst,             Ah + ga);
            cp_async16(dst + GMAT,      Al + ga);
            cp_async16(dst + 2 * GMAT,  Bh + gb);
            cp_async16(dst + 3 * GMAT,  Bl + gb);
        }
    };

    // prologue: chunks 0 .. GS-2
#pragma unroll
    for (int s = 0; s < GS - 1; s++) { load_stage(s, s * 32); cp_commit(); }

    for (int k = 0; k < nk; k++) {
        cp_wait<GS - 2>();        // chunk k resident (thread-local)
        __syncthreads();          // visible to all; all done computing chunk k-1
        // issue chunk k+GS-1 into stage (k+GS-1)%GS (held chunk k-1, now free)
        if (k + GS - 1 < nk) load_stage((k + GS - 1) % GS, (k + GS - 1) * 32);
        cp_commit();

        const uint32_t stage = sb + (k % GS) * GSTAGE;
        const uint32_t* wAh = reinterpret_cast<const uint32_t*>(smem) + (stage - sb) / 4;
        const uint32_t* wAl = wAh + GMAT / 4;
        const uint32_t* wBh = wAh + 2 * GMAT / 4;
        const uint32_t* wBl = wAh + 3 * GMAT / 4;

#pragma unroll
        for (int kt = 0; kt < 2; kt++) {
            uint32_t afh[4][4], afl[4][4];
#pragma unroll
            for (int mt = 0; mt < 4; mt++) {
                const int base = (wm * 64 + mt * 16 + g) * 20 + kt * 8 + t;
                afh[mt][0] = wAh[base];       afh[mt][1] = wAh[base + 160];
                afh[mt][2] = wAh[base + 4];   afh[mt][3] = wAh[base + 164];
                afl[mt][0] = wAl[base];       afl[mt][1] = wAl[base + 160];
                afl[mt][2] = wAl[base + 4];   afl[mt][3] = wAl[base + 164];
            }
#pragma unroll
            for (int nt = 0; nt < 4; nt++) {
                const int nb = (wn * 32 + nt * 8 + g) * 20 + kt * 8 + t;
                const uint32_t b0h = wBh[nb], b1h = wBh[nb + 4];
                const uint32_t b0l = wBl[nb], b1l = wBl[nb + 4];
#pragma unroll
                for (int mt = 0; mt < 4; mt++) {
                    mma16816(c[mt][nt], afh[mt], b0h, b1h);
                    mma16816(c[mt][nt], afh[mt], b0l, b1l);
                    mma16816(c[mt][nt], afl[mt], b0h, b1h);
                }
            }
        }
    }

    // epilogue
#pragma unroll
    for (int mt = 0; mt < 4; mt++) {
        const int row = bm + wm * 64 + mt * 16 + g;
#pragma unroll
        for (int nt = 0; nt < 4; nt++) {
            const int col = bn + wn * 32 + nt * 8 + 2 * t;
            *reinterpret_cast<float2*>(&C[(size_t)row * N + col]) =
                make_float2(c[mt][nt][0], c[mt][nt][1]);
            *reinterpret_cast<float2*>(&C[(size_t)(row + 8) * N + col]) =
                make_float2(c[mt][nt][2], c[mt][nt][3]);
        }
    }
}

// ---------------------------------------------------------------------------
// Elementwise hi/lo split (row-major): fp32 -> 2x bf16
// ---------------------------------------------------------------------------
__global__ void split_rm(const float4* __restrict__ A, uint2* __restrict__ H,
                         uint2* __restrict__ L, int n4) {
    int i = blockIdx.x * blockDim.x + threadIdx.x;
    if (i >= n4) return;
    float4 v = A[i];
    __nv_bfloat162 h0 = __floats2bfloat162_rn(v.x, v.y);
    __nv_bfloat162 h1 = __floats2bfloat162_rn(v.z, v.w);
    __nv_bfloat162 l0 = __floats2bfloat162_rn(v.x - __bfloat162float(h0.x),
                                              v.y - __bfloat162float(h0.y));
    __nv_bfloat162 l1 = __floats2bfloat162_rn(v.z - __bfloat162float(h1.x),
                                              v.w - __bfloat162float(h1.y));
    H[i] = make_uint2(*reinterpret_cast<uint32_t*>(&h0), *reinterpret_cast<uint32_t*>(&h1));
    L[i] = make_uint2(*reinterpret_cast<uint32_t*>(&l0), *reinterpret_cast<uint32_t*>(&l1));
}

// ---------------------------------------------------------------------------
// Transpose + split: W (K x N) fp32 -> TH/TL (N x K) bf16
// ---------------------------------------------------------------------------
__global__ __launch_bounds__(256) void split_wt(const float* __restrict__ W,
                                                __nv_bfloat16* __restrict__ TH,
                                                __nv_bfloat16* __restrict__ TL,
                                                int K, int N) {
    __shared__ float tile[32][33];
    const int kb = blockIdx.x * 32, nb = blockIdx.y * 32;
    const int tx = threadIdx.x & 31, ty = threadIdx.x >> 5;
#pragma unroll
    for (int r = ty; r < 32; r += 8)
        tile[r][tx] = W[(size_t)(kb + r) * N + nb + tx];
    __syncthreads();
#pragma unroll
    for (int r = ty; r < 32; r += 8) {
        float v = tile[tx][r];
        __nv_bfloat16 h = __float2bfloat16(v);
        TH[(size_t)(nb + r) * K + kb + tx] = h;
        TL[(size_t)(nb + r) * K + kb + tx] = __float2bfloat16(v - __bfloat162float(h));
    }
}

// ---------------------------------------------------------------------------
// Attention prep: g_qkv -> per-head split Q (scaled), K, transposed V.
// ---------------------------------------------------------------------------
__global__ __launch_bounds__(256) void attn_prep() {
    __shared__ float sV[128][65];
    const int tid = threadIdx.x;
    const int bh = blockIdx.y;
    const int b = bh >> 4, h = bh & 15;
    const int t0 = blockIdx.x * 128;
    const float* base = g_qkv + ((size_t)(b * T_SEQ + t0)) * QKV_COLS + h * 192;

    for (int i = tid; i < 128 * 64; i += 256) {
        const int tt = i >> 6, d = i & 63;
        const float* rp = base + (size_t)tt * QKV_COLS;
        const size_t o = ((size_t)bh * T_SEQ + t0 + tt) * HDIM + d;
        float q = rp[d] * 0.125f;
        __nv_bfloat16 qh = __float2bfloat16(q);
        gQh[o] = qh; gQl[o] = __float2bfloat16(q - __bfloat162float(qh));
        float k = rp[64 + d];
        __nv_bfloat16 kh = __float2bfloat16(k);
        gKh[o] = kh; gKl[o] = __float2bfloat16(k - __bfloat162float(kh));
        sV[tt][d] = rp[128 + d];
    }
    __syncthreads();
    for (int j = tid; j < 64 * 128; j += 256) {
        const int d = j >> 7, tt = j & 127;
        float v = sV[tt][d];
        __nv_bfloat16 vh = __float2bfloat16(v);
        const size_t o = ((size_t)bh * HDIM + d) * T_SEQ + t0 + tt;
        gVth[o] = vh; gVtl[o] = __float2bfloat16(v - __bfloat162float(vh));
    }
}

// ===========================================================================
// Flash attention v2: bf16 mma.sync (x3), 2-stage cp.async KV pipeline.
// grid (T/128, BH), 256 threads. Warp w owns query rows [qb+16w, qb+16w+16).
// smem per stage per matrix: 64 rows * 144 B (72 bf16 stride; 16B aligned,
// conflict-free at 36-word stride). 4 matrices * 2 stages = 73728 B dynamic.
// ===========================================================================
#define AMAT    9216                        // 64 * 144
#define ASTAGE  (4 * AMAT)                  // Kh,Kl,Vh,Vl
#define ATT_SMEM (2 * ASTAGE)               // 73728

__global__ __launch_bounds__(256, 1) void attn_mma() {
    extern __shared__ __align__(16) char smem[];
    const uint32_t sb = smem_u32(smem);

    const int tid = threadIdx.x;
    const int lane = tid & 31, warp = tid >> 5;
    const int g = lane >> 2, t = lane & 3;
    const int qblk = blockIdx.x, bh = blockIdx.y;
    const int qb = qblk * 128;
    const int qrow = qb + warp * 16 + g;

    // Q fragments (held for the whole kernel)
    const uint32_t* gqh = reinterpret_cast<const uint32_t*>(gQh + (size_t)bh * T_SEQ * HDIM);
    const uint32_t* gql = reinterpret_cast<const uint32_t*>(gQl + (size_t)bh * T_SEQ * HDIM);
    uint32_t qfh[4][4], qfl[4][4];
#pragma unroll
    for (int k4 = 0; k4 < 4; k4++) {
        const int w0 = qrow * 32 + k4 * 8 + t;
        qfh[k4][0] = gqh[w0];       qfh[k4][1] = gqh[w0 + 256];
        qfh[k4][2] = gqh[w0 + 4];   qfh[k4][3] = gqh[w0 + 260];
        qfl[k4][0] = gql[w0];       qfl[k4][1] = gql[w0 + 256];
        qfl[k4][2] = gql[w0 + 4];   qfl[k4][3] = gql[w0 + 260];
    }

    float o[8][4];
#pragma unroll
    for (int i = 0; i < 8; i++)
#pragma unroll
        for (int j = 0; j < 4; j++) o[i][j] = 0.0f;
    float m0 = -1e30f, m1 = -1e30f, l0 = 0.0f, l1 = 0.0f;

    const int nkt = 2 * qblk + 2;

    // cp.async loader: 2048 16B chunks per stage, 8 per thread
    auto load_stage = [&](int s, int kt) {
        const uint32_t stage = sb + s * ASTAGE;
#pragma unroll
        for (int j = 0; j < 8; j++) {
            const int i   = tid + j * 256;       // 0..2047
            const int mat = i >> 9;              // 0..3
            const int r   = (i >> 3) & 63;
            const int ch  = i & 7;
            const uint32_t dst = stage + mat * AMAT + r * 144 + ch * 16;
            const __nv_bfloat16* src;
            if (mat < 2) {
                const size_t off = ((size_t)bh * T_SEQ + kt * 64 + r) * HDIM + ch * 8;
                src = (mat == 0 ? gKh : gKl) + off;
            } else {
                const size_t off = ((size_t)bh * HDIM + r) * T_SEQ + kt * 64 + ch * 8;
                src = (mat == 2 ? gVth : gVtl) + off;
            }
            cp_async16(dst, src);
        }
    };

    load_stage(0, 0);
    cp_commit();

    for (int kt = 0; kt < nkt; kt++) {
        cp_wait<0>();
        __syncthreads();       // stage kt visible; all warps done with stage kt-1
        if (kt + 1 < nkt) load_stage((kt + 1) & 1, kt + 1);
        cp_commit();

        const uint32_t stage_off = ((kt & 1) * ASTAGE) / 4;
        const uint32_t* wKh = reinterpret_cast<const uint32_t*>(smem) + stage_off;
        const uint32_t* wKl = wKh + AMAT / 4;
        const uint32_t* wVh = wKh + 2 * AMAT / 4;
        const uint32_t* wVl = wKh + 3 * AMAT / 4;

        // ---- S = Q K^T (x3) ----
        float s[8][4];
#pragma unroll
        for (int i = 0; i < 8; i++)
#pragma unroll
            for (int j = 0; j < 4; j++) s[i][j] = 0.0f;

#pragma unroll
        for (int k4 = 0; k4 < 4; k4++) {
#pragma unroll
            for (int nt = 0; nt < 8; nt++) {
                const int kb = (nt * 8 + g) * 36 + k4 * 8 + t;
                const uint32_t b0h = wKh[kb], b1h = wKh[kb + 4];
                const uint32_t b0l = wKl[kb], b1l = wKl[kb + 4];
                mma16816(s[nt], qfh[k4], b0h, b1h);
                mma16816(s[nt], qfh[k4], b0l, b1l);
                mma16816(s[nt], qfl[k4], b0h, b1h);
            }
        }

        // ---- causal mask on diagonal tiles ----
        if (kt >= 2 * qblk) {
#pragma unroll
            for (int nt = 0; nt < 8; nt++) {
                const int colb = kt * 64 + nt * 8 + 2 * t;
                if (colb     > qrow)     s[nt][0] = -1e30f;
                if (colb + 1 > qrow)     s[nt][1] = -1e30f;
                if (colb     > qrow + 8) s[nt][2] = -1e30f;
                if (colb + 1 > qrow + 8) s[nt][3] = -1e30f;
            }
        }

        // ---- online softmax (warp-local rows) ----
        float mx0 = -1e30f, mx1 = -1e30f;
#pragma unroll
        for (int nt = 0; nt < 8; nt++) {
            mx0 = fmaxf(mx0, fmaxf(s[nt][0], s[nt][1]));
            mx1 = fmaxf(mx1, fmaxf(s[nt][2], s[nt][3]));
        }
        mx0 = fmaxf(mx0, __shfl_xor_sync(0xffffffffu, mx0, 1));
        mx0 = fmaxf(mx0, __shfl_xor_sync(0xffffffffu, mx0, 2));
        mx1 = fmaxf(mx1, __shfl_xor_sync(0xffffffffu, mx1, 1));
        mx1 = fmaxf(mx1, __shfl_xor_sync(0xffffffffu, mx1, 2));
        const float mn0 = fmaxf(m0, mx0), mn1 = fmaxf(m1, mx1);
        const float sc0 = __expf(m0 - mn0), sc1 = __expf(m1 - mn1);
        float sum0 = 0.0f, sum1 = 0.0f;
#pragma unroll
        for (int nt = 0; nt < 8; nt++) {
            s[nt][0] = __expf(s[nt][0] - mn0); sum0 += s[nt][0];
            s[nt][1] = __expf(s[nt][1] - mn0); sum0 += s[nt][1];
            s[nt][2] = __expf(s[nt][2] - mn1); sum1 += s[nt][2];
            s[nt][3] = __expf(s[nt][3] - mn1); sum1 += s[nt][3];
        }
        sum0 += __shfl_xor_sync(0xffffffffu, sum0, 1);
        sum0 += __shfl_xor_sync(0xffffffffu, sum0, 2);
        sum1 += __shfl_xor_sync(0xffffffffu, sum1, 1);
        sum1 += __shfl_xor_sync(0xffffffffu, sum1, 2);
        l0 = l0 * sc0 + sum0; m0 = mn0;
        l1 = l1 * sc1 + sum1; m1 = mn1;
#pragma unroll
        for (int nt = 0; nt < 8; nt++) {
            o[nt][0] *= sc0; o[nt][1] *= sc0;
            o[nt][2] *= sc1; o[nt][3] *= sc1;
        }

        // ---- O += P V (x3); P fragments built in registers ----
#pragma unroll
        for (int kp = 0; kp < 4; kp++) {
            const float* pa = s[2 * kp];
            const float* pb = s[2 * kp + 1];
            uint32_t ah[4], al[4];
            {
                __nv_bfloat162 h0 = __floats2bfloat162_rn(pa[0], pa[1]);
                __nv_bfloat162 h1 = __floats2bfloat162_rn(pa[2], pa[3]);
                __nv_bfloat162 h2 = __floats2bfloat162_rn(pb[0], pb[1]);
                __nv_bfloat162 h3 = __floats2bfloat162_rn(pb[2], pb[3]);
                ah[0] = *reinterpret_cast<uint32_t*>(&h0);
                ah[1] = *reinterpret_cast<uint32_t*>(&h1);
                ah[2] = *reinterpret_cast<uint32_t*>(&h2);
                ah[3] = *reinterpret_cast<uint32_t*>(&h3);
                __nv_bfloat162 e0 = __floats2bfloat162_rn(pa[0] - __bfloat162float(h0.x),
                                                          pa[1] - __bfloat162float(h0.y));
                __nv_bfloat162 e1 = __floats2bfloat162_rn(pa[2] - __bfloat162float(h1.x),
                                                          pa[3] - __bfloat162float(h1.y));
                __nv_bfloat162 e2 = __floats2bfloat162_rn(pb[0] - __bfloat162float(h2.x),
                                                          pb[1] - __bfloat162float(h2.y));
                __nv_bfloat162 e3 = __floats2bfloat162_rn(pb[2] - __bfloat162float(h3.x),
                                                          pb[3] - __bfloat162float(h3.y));
                al[0] = *reinterpret_cast<uint32_t*>(&e0);
                al[1] = *reinterpret_cast<uint32_t*>(&e1);
                al[2] = *reinterpret_cast<uint32_t*>(&e2);
                al[3] = *reinterpret_cast<uint32_t*>(&e3);
            }
#pragma unroll
            for (int nd = 0; nd < 8; nd++) {
                const int vb = (nd * 8 + g) * 36 + kp * 8 + t;
                const uint32_t b0h = wVh[vb], b1h = wVh[vb + 4];
                const uint32_t b0l = wVl[vb], b1l = wVl[vb + 4];
                mma16816(o[nd], ah, b0h, b1h);
                mma16816(o[nd], ah, b0l, b1l);
                mma16816(o[nd], al, b0h, b1h);
            }
        }
    }

    // ---- epilogue: normalize, emit hi/lo bf16 split ----
    const float inv0 = 1.0f / l0, inv1 = 1.0f / l1;
#pragma unroll
    for (int nd = 0; nd < 8; nd++) {
        const size_t flat = ((size_t)bh * T_SEQ + qb + warp * 16 + g) * HDIM + nd * 8 + 2 * t;
        {
            const float v0 = o[nd][0] * inv0, v1 = o[nd][1] * inv0;
            __nv_bfloat162 hh = __floats2bfloat162_rn(v0, v1);
            *reinterpret_cast<uint32_t*>(gVAh + flat) = *reinterpret_cast<uint32_t*>(&hh);
            __nv_bfloat162 ll = __floats2bfloat162_rn(v0 - __bfloat162float(hh.x),
                                                      v1 - __bfloat162float(hh.y));
            *reinterpret_cast<uint32_t*>(gVAl + flat) = *reinterpret_cast<uint32_t*>(&ll);
        }
        {
            const size_t f8 = flat + 8 * HDIM;
            const float v0 = o[nd][2] * inv1, v1 = o[nd][3] * inv1;
            __nv_bfloat162 hh = __floats2bfloat162_rn(v0, v1);
            *reinterpret_cast<uint32_t*>(gVAh + f8) = *reinterpret_cast<uint32_t*>(&hh);
            __nv_bfloat162 ll = __floats2bfloat162_rn(v0 - __bfloat162float(hh.x),
                                                      v1 - __bfloat162float(hh.y));
            *reinterpret_cast<uint32_t*>(gVAl + f8) = *reinterpret_cast<uint32_t*>(&ll);
        }
    }
}

// ---------------------------------------------------------------------------
// kernel_launch
// ---------------------------------------------------------------------------
extern "C" void kernel_launch(void* const* d_in, const int* in_sizes, int n_in,
                              void* d_out, int out_size) {
    const float* x    = (const float*)d_in[0];
    const float* wqkv = (const float*)d_in[1];
    const float* wout = (const float*)d_in[2];
    float*       out  = (float*)d_out;

    float* qkv; __nv_bfloat16 *xh, *xl, *wqh, *wql, *woh, *wol, *vah, *vaL;
    cudaGetSymbolAddress((void**)&qkv, g_qkv);
    cudaGetSymbolAddress((void**)&xh,  gXh);  cudaGetSymbolAddress((void**)&xl,  gXl);
    cudaGetSymbolAddress((void**)&wqh, gWqh); cudaGetSymbolAddress((void**)&wql, gWql);
    cudaGetSymbolAddress((void**)&woh, gWoh); cudaGetSymbolAddress((void**)&wol, gWol);
    cudaGetSymbolAddress((void**)&vah, gVAh); cudaGetSymbolAddress((void**)&vaL, gVAl);

    cudaFuncSetAttribute(gemm_bf16x3, cudaFuncAttributeMaxDynamicSharedMemorySize, GEMM_SMEM);
    cudaFuncSetAttribute(attn_mma,    cudaFuncAttributeMaxDynamicSharedMemorySize, ATT_SMEM);

    // 1) splits of inputs
    const int n4x = ROWS * D_MODEL / 4;
    split_rm<<<(n4x + 255) / 256, 256>>>((const float4*)x, (uint2*)xh, (uint2*)xl, n4x);
    split_wt<<<dim3(D_MODEL / 32, QKV_COLS / 32), 256>>>(wqkv, wqh, wql, D_MODEL, QKV_COLS);
    split_wt<<<dim3(D_MODEL / 32, D_MODEL / 32), 256>>>(wout, woh, wol, D_MODEL, D_MODEL);

    // 2) qkv = x @ w_qkv
    gemm_bf16x3<<<dim3(QKV_COLS / 128, ROWS / 128), 256, GEMM_SMEM>>>(
        xh, xl, wqh, wql, qkv, ROWS, QKV_COLS, D_MODEL);

    // 3) per-head prep
    attn_prep<<<dim3(T_SEQ / 128, BH), 256>>>();

    // 4) flash attention
    attn_mma<<<dim3(T_SEQ / 128, BH), 256, ATT_SMEM>>>();

    // 5) out = vals @ w_out
    gemm_bf16x3<<<dim3(D_MODEL / 128, ROWS / 128), 256, GEMM_SMEM>>>(
        vah, vaL, woh, wol, out, ROWS, D_MODEL, D_MODEL);
}